// round 13
// baseline (speedup 1.0000x reference)
#include <cuda_runtime.h>
#include <math.h>
#include <stdint.h>

#define C      256
#define RBF    64
#define EPB    32     // edges per block  (4 groups x 8 edges)
#define NPB    32     // nodes per block  (4 groups x 8 nodes)
#define N_MAX  50000

// Scratch (no cudaMalloc allowed anywhere).
__device__ float g_agg[(size_t)N_MAX * C];

typedef unsigned long long u64t;

// ---- packed f32x2 helpers ----
__device__ __forceinline__ u64t pack2(float lo, float hi) {
    u64t d; asm("mov.b64 %0, {%1, %2};" : "=l"(d) : "f"(lo), "f"(hi)); return d;
}
__device__ __forceinline__ void unpack2(u64t v, float& lo, float& hi) {
    asm("mov.b64 {%0, %1}, %2;" : "=f"(lo), "=f"(hi) : "l"(v));
}
__device__ __forceinline__ u64t ffma2(u64t a, u64t b, u64t c) {
    u64t d; asm("fma.rn.f32x2 %0, %1, %2, %3;" : "=l"(d) : "l"(a), "l"(b), "l"(c));
    return d;
}

// ---------------------------------------------------------------------------
__global__ void zero_agg_kernel(int total4) {
    float4 z = make_float4(0.f, 0.f, 0.f, 0.f);
    float4* p = (float4*)g_agg;
    for (int i = blockIdx.x * blockDim.x + threadIdx.x; i < total4;
         i += gridDim.x * blockDim.x)
        p[i] = z;
}

// ---------------------------------------------------------------------------
// Edge stage:  agg[r] += embed[z[sender]] * ((cut*ef) @ W_dist + cut*b)
// 256 threads = 4 groups x 64; group = 8 edges (4 packed pairs), thread = 4 ch.
// GEMM inner: W preloaded in 4-k batches (4x LDG.128, MLP overlap); edge-pair
// operands via LDS.128 covering two k-steps at once.
// ---------------------------------------------------------------------------
__global__ __launch_bounds__(256, 3) void edge_kernel(
    const int*   __restrict__ node_z,
    const int*   __restrict__ senders,
    const int*   __restrict__ receivers,
    const float* __restrict__ edge_weight,
    const float* __restrict__ edge_feats,
    const float* __restrict__ embed_table,
    const float* __restrict__ W_dist,
    const float* __restrict__ b_dist,
    int E)
{
    __shared__ float ef2[EPB / 2][RBF][2];   // 8 KB: y = cut*ef, pair-interleaved
    __shared__ int   sp_sh[EPB];
    __shared__ int   r_sh[EPB];
    __shared__ float cut_sh[EPB];

    const int e0  = blockIdx.x * EPB;
    const int tid = threadIdx.x;
    const int ne  = min(EPB, E - e0);

    if (tid < EPB) {
        if (tid < ne) {
            int e = e0 + tid;
            sp_sh[tid] = node_z[senders[e]];
            r_sh[tid]  = receivers[e];
            float w = edge_weight[e];
            float cutv = 0.5f * (__cosf(w * 0.62831853071795864769f) + 1.0f); // pi/5
            cut_sh[tid] = (w < 5.0f) ? cutv : 0.0f;
        } else {                     // pad edges contribute exactly zero
            sp_sh[tid]  = 0;
            r_sh[tid]   = receivers[e0 + ne - 1];
            cut_sh[tid] = 0.0f;
        }
    }
    __syncthreads();

    // stage y = cut*ef, pair-interleaved (pad rows zero)
    {
        const float4* src = (const float4*)(edge_feats + (size_t)e0 * RBF);
        for (int idx = tid; idx < EPB * 16; idx += 256) {
            int e = idx >> 4, j = idx & 15;
            float4 v = (e < ne) ? src[idx] : make_float4(0.f, 0.f, 0.f, 0.f);
            float ct = cut_sh[e];
            int p = e >> 1, h = e & 1, k = 4 * j;
            ef2[p][k + 0][h] = v.x * ct;
            ef2[p][k + 1][h] = v.y * ct;
            ef2[p][k + 2][h] = v.z * ct;
            ef2[p][k + 3][h] = v.w * ct;
        }
    }
    __syncthreads();

    const int g   = tid >> 6;          // edge group 0..3  (8 edges each)
    const int t64 = tid & 63;
    const int c4  = t64 * 4;           // 4 consecutive channels
    const int p0  = g * 4;             // this group's 4 edge-pairs

    // ---- GEMM: P[pair][ch] accumulators (16 u64 = 32 regs) ----
    u64t acc2[4][4];
    #pragma unroll
    for (int p = 0; p < 4; p++)
        #pragma unroll
        for (int q = 0; q < 4; q++) acc2[p][q] = 0ull;

    #pragma unroll 2
    for (int kc = 0; kc < RBF; kc += 4) {
        // batched W loads for 4 k-steps (MLP-4, L1-hot)
        float4 wv[4];
        #pragma unroll
        for (int i = 0; i < 4; i++)
            wv[i] = *(const float4*)(W_dist + (size_t)(kc + i) * C + c4);

        #pragma unroll
        for (int kk = 0; kk < 4; kk += 2) {
            u64t wA0 = pack2(wv[kk].x, wv[kk].x);
            u64t wA1 = pack2(wv[kk].y, wv[kk].y);
            u64t wA2 = pack2(wv[kk].z, wv[kk].z);
            u64t wA3 = pack2(wv[kk].w, wv[kk].w);
            u64t wB0 = pack2(wv[kk + 1].x, wv[kk + 1].x);
            u64t wB1 = pack2(wv[kk + 1].y, wv[kk + 1].y);
            u64t wB2 = pack2(wv[kk + 1].z, wv[kk + 1].z);
            u64t wB3 = pack2(wv[kk + 1].w, wv[kk + 1].w);
            #pragma unroll
            for (int p = 0; p < 4; p++) {
                // one LDS.128: pair p operands for k-steps kc+kk and kc+kk+1
                ulonglong2 y = *(const ulonglong2*)&ef2[p0 + p][kc + kk][0];
                acc2[p][0] = ffma2(y.x, wA0, acc2[p][0]);
                acc2[p][1] = ffma2(y.x, wA1, acc2[p][1]);
                acc2[p][2] = ffma2(y.x, wA2, acc2[p][2]);
                acc2[p][3] = ffma2(y.x, wA3, acc2[p][3]);
                acc2[p][0] = ffma2(y.y, wB0, acc2[p][0]);
                acc2[p][1] = ffma2(y.y, wB1, acc2[p][1]);
                acc2[p][2] = ffma2(y.y, wB2, acc2[p][2]);
                acc2[p][3] = ffma2(y.y, wB3, acc2[p][3]);
            }
        }
    }

    // ---- epilogue: sorted-run accumulation over this group's 8 edges ----
    const float4 bd4 = *(const float4*)(b_dist + c4);
    float a0 = 0.f, a1 = 0.f, a2 = 0.f, a3 = 0.f;
    int   cur = -1;

    #pragma unroll
    for (int i = 0; i < 8; i++) {
        const int e = g * 8 + i;
        const int p = i >> 1;
        const int h = i & 1;

        float P0, P1, P2, P3;
        {
            float lo, hi;
            unpack2(acc2[p][0], lo, hi); P0 = h ? hi : lo;
            unpack2(acc2[p][1], lo, hi); P1 = h ? hi : lo;
            unpack2(acc2[p][2], lo, hi); P2 = h ? hi : lo;
            unpack2(acc2[p][3], lo, hi); P3 = h ? hi : lo;
        }

        int r = r_sh[e];
        if (r != cur) {
            if (cur >= 0) {
                float* dst = &g_agg[(size_t)cur * C + c4];
                atomicAdd(dst + 0, a0); atomicAdd(dst + 1, a1);
                atomicAdd(dst + 2, a2); atomicAdd(dst + 3, a3);
            }
            a0 = a1 = a2 = a3 = 0.f;
            cur = r;
        }
        float  ct = cut_sh[e];
        float4 xj = *(const float4*)(embed_table + (size_t)sp_sh[e] * C + c4);
        a0 = fmaf(xj.x, fmaf(ct, bd4.x, P0), a0);
        a1 = fmaf(xj.y, fmaf(ct, bd4.y, P1), a1);
        a2 = fmaf(xj.z, fmaf(ct, bd4.z, P2), a2);
        a3 = fmaf(xj.w, fmaf(ct, bd4.w, P3), a3);
    }
    if (cur >= 0) {
        float* dst = &g_agg[(size_t)cur * C + c4];
        atomicAdd(dst + 0, a0); atomicAdd(dst + 1, a1);
        atomicAdd(dst + 2, a2); atomicAdd(dst + 3, a3);
    }
}

// ---------------------------------------------------------------------------
// Stage B: out = concat(node_feats, agg) @ W_comb + b_comb
// Per k-step per thread: 1 LDG.128 + 2 LDS.128 (two pairs each) + 16 FFMA2.
// 4 CTAs/SM for phase overlap.  K=512 in 8 tiles of 64.
// ---------------------------------------------------------------------------
__global__ __launch_bounds__(256, 4) void node_kernel(
    const float* __restrict__ node_feats,
    const float* __restrict__ W_comb,
    const float* __restrict__ b_comb,
    float*       __restrict__ out,
    int n_nodes)
{
    __shared__ float x2[64][NPB / 2][2];   // 8 KB, [k][pair][half]

    const int n0  = blockIdx.x * NPB;
    const int tid = threadIdx.x;
    const int nn  = min(NPB, n_nodes - n0);

    const int g   = tid >> 6;          // node group 0..3 (8 nodes each)
    const int t64 = tid & 63;
    const int c4  = t64 * 4;
    const int p0  = g * 4;

    u64t acc2[4][4];
    #pragma unroll
    for (int p = 0; p < 4; p++)
        #pragma unroll
        for (int q = 0; q < 4; q++) acc2[p][q] = 0ull;

    for (int kb = 0; kb < 8; kb++) {
        const float* srcbase = (kb < 4) ? node_feats : g_agg;
        const int    off     = (kb & 3) * 64;

        for (int idx = tid; idx < NPB * 16; idx += 256) {
            int row = idx >> 4, j = idx & 15;
            float4 v = (row < nn)
                ? ((const float4*)(srcbase + (size_t)(n0 + row) * C + off))[j]
                : make_float4(0.f, 0.f, 0.f, 0.f);
            int p = row >> 1, h = row & 1, k = 4 * j;
            x2[k + 0][p][h] = v.x;
            x2[k + 1][p][h] = v.y;
            x2[k + 2][p][h] = v.z;
            x2[k + 3][p][h] = v.w;
        }
        __syncthreads();

        const float* Wk = W_comb + (size_t)(kb * 64) * C + c4;
        #pragma unroll 4
        for (int k = 0; k < 64; k++) {
            float4 wv = *(const float4*)(Wk + (size_t)k * C);   // coalesced
            u64t w0 = pack2(wv.x, wv.x);
            u64t w1 = pack2(wv.y, wv.y);
            u64t w2 = pack2(wv.z, wv.z);
            u64t w3 = pack2(wv.w, wv.w);
            // two LDS.128: pairs (p0,p0+1) and (p0+2,p0+3) for this k
            ulonglong2 xA = *(const ulonglong2*)&x2[k][p0][0];
            ulonglong2 xB = *(const ulonglong2*)&x2[k][p0 + 2][0];
            acc2[0][0] = ffma2(xA.x, w0, acc2[0][0]);
            acc2[0][1] = ffma2(xA.x, w1, acc2[0][1]);
            acc2[0][2] = ffma2(xA.x, w2, acc2[0][2]);
            acc2[0][3] = ffma2(xA.x, w3, acc2[0][3]);
            acc2[1][0] = ffma2(xA.y, w0, acc2[1][0]);
            acc2[1][1] = ffma2(xA.y, w1, acc2[1][1]);
            acc2[1][2] = ffma2(xA.y, w2, acc2[1][2]);
            acc2[1][3] = ffma2(xA.y, w3, acc2[1][3]);
            acc2[2][0] = ffma2(xB.x, w0, acc2[2][0]);
            acc2[2][1] = ffma2(xB.x, w1, acc2[2][1]);
            acc2[2][2] = ffma2(xB.x, w2, acc2[2][2]);
            acc2[2][3] = ffma2(xB.x, w3, acc2[2][3]);
            acc2[3][0] = ffma2(xB.y, w0, acc2[3][0]);
            acc2[3][1] = ffma2(xB.y, w1, acc2[3][1]);
            acc2[3][2] = ffma2(xB.y, w2, acc2[3][2]);
            acc2[3][3] = ffma2(xB.y, w3, acc2[3][3]);
        }
        __syncthreads();
    }

    const float4 b4 = *(const float4*)(b_comb + c4);
    #pragma unroll
    for (int i = 0; i < 8; i++) {
        const int row = g * 8 + i;
        if (row < nn) {
            const int p = i >> 1, h = i & 1;
            float lo, hi, v0, v1, v2, v3;
            unpack2(acc2[p][0], lo, hi); v0 = (h ? hi : lo) + b4.x;
            unpack2(acc2[p][1], lo, hi); v1 = (h ? hi : lo) + b4.y;
            unpack2(acc2[p][2], lo, hi); v2 = (h ? hi : lo) + b4.z;
            unpack2(acc2[p][3], lo, hi); v3 = (h ? hi : lo) + b4.w;
            *(float4*)(out + (size_t)(n0 + row) * C + c4) =
                make_float4(v0, v1, v2, v3);                // STG.128
        }
    }
}

// ---------------------------------------------------------------------------
extern "C" void kernel_launch(void* const* d_in, const int* in_sizes, int n_in,
                              void* d_out, int out_size)
{
    const int*   node_z      = (const int*)  d_in[0];
    const float* node_feats  = (const float*)d_in[1];
    const int*   senders     = (const int*)  d_in[2];
    const int*   receivers   = (const int*)  d_in[3];
    const float* edge_weight = (const float*)d_in[4];
    const float* edge_feats  = (const float*)d_in[5];
    const float* embed_table = (const float*)d_in[6];
    const float* W_dist      = (const float*)d_in[7];
    const float* b_dist      = (const float*)d_in[8];
    const float* W_comb      = (const float*)d_in[9];
    const float* b_comb      = (const float*)d_in[10];
    float* out = (float*)d_out;

    const int n_nodes = in_sizes[0];   // 50000
    const int E       = in_sizes[2];   // 800000

    zero_agg_kernel<<<2048, 256>>>(n_nodes * C / 4);

    edge_kernel<<<(E + EPB - 1) / EPB, 256>>>(
        node_z, senders, receivers, edge_weight, edge_feats,
        embed_table, W_dist, b_dist, E);

    node_kernel<<<(n_nodes + NPB - 1) / NPB, 256>>>(
        node_feats, W_comb, b_comb, out, n_nodes);
}